// round 15
// baseline (speedup 1.0000x reference)
#include <cuda_runtime.h>
#include <cuda_fp16.h>
#include <cstdint>

#define E_ 11
#define B_ 1024
#define D_ 1536
#define H_ 3072
#define C_ 5242
#define CP_ 5248

#define BM 128
#define BN 64
#define BK 16
#define NTHREADS 128              // 4 warps: 2 (M) x 2 (N), warp tile 64x32
#define MT 2
#define NSPLIT 2

#define SAS 24                    // A fp16 tile stride (halves)
#define SA_B (BM * SAS * 2)       // 6144 B per A slot (5 slots)
#define SBS 72                    // B fp16 tile stride (halves), BN=64
#define B64_B (BK * SBS * 2)      // 2304 B per B slot (2 slots)

// ---- scratch ----
__device__ int    g_cnt[E_];
__device__ int    g_idx[E_ * B_];
__device__ int    g_bin[B_];
__device__ __half g_x16[(size_t)B_ * D_];
__device__ __half g_h1[(size_t)B_ * H_];
__device__ __half g_h2[(size_t)B_ * H_];
__device__ float  g_p0[(size_t)B_ * CP_];
__device__ float  g_p1[(size_t)B_ * CP_];

// ---------------------------------------------------------------------------
__global__ void route_kernel(const float* __restrict__ mf) {
    int tid = threadIdx.x;
    if (tid < E_) g_cnt[tid] = 0;
    __syncthreads();
    float t = 1.0f - mf[tid];
    float q = t / 0.1f;               // IEEE div, matches XLA lowering
    int bin = (int)q;
    bin = max(0, min(E_ - 1, bin));
    g_bin[tid] = bin;
    int pos = atomicAdd(&g_cnt[bin], 1);
    g_idx[bin * B_ + pos] = tid;
}

// x fp32 -> fp16 (so L1 uses the same fast GEMM path)
__global__ void cvt_x_kernel(const float* __restrict__ x) {
    const int r = blockIdx.x;
    const float* src = x + (size_t)r * D_;
    __half* dst = g_x16 + (size_t)r * D_;
    for (int i = threadIdx.x * 4; i < D_; i += 1024) {
        float4 v = *reinterpret_cast<const float4*>(src + i);
        __half2 h0 = __float22half2_rn(make_float2(v.x, v.y));
        __half2 h1 = __float22half2_rn(make_float2(v.z, v.w));
        *reinterpret_cast<__half2*>(dst + i) = h0;
        *reinterpret_cast<__half2*>(dst + i + 2) = h1;
    }
}

// ---- PTX helpers ----------------------------------------------------------
__device__ __forceinline__ void cp_async16(uint32_t s, const void* g) {
    asm volatile("cp.async.cg.shared.global [%0], [%1], 16;\n" :: "r"(s), "l"(g));
}
__device__ __forceinline__ void cp_commit() {
    asm volatile("cp.async.commit_group;\n" ::: "memory");
}
template <int N>
__device__ __forceinline__ void cp_wait() {
    asm volatile("cp.async.wait_group %0;\n" :: "n"(N) : "memory");
}
__device__ __forceinline__ void ldsm4(uint32_t r[4], uint32_t addr) {
    asm volatile("ldmatrix.sync.aligned.m8n8.x4.shared.b16 {%0,%1,%2,%3}, [%4];"
                 : "=r"(r[0]), "=r"(r[1]), "=r"(r[2]), "=r"(r[3]) : "r"(addr));
}
__device__ __forceinline__ void ldsm4t(uint32_t r[4], uint32_t addr) {
    asm volatile("ldmatrix.sync.aligned.m8n8.x4.trans.shared.b16 {%0,%1,%2,%3}, [%4];"
                 : "=r"(r[0]), "=r"(r[1]), "=r"(r[2]), "=r"(r[3]) : "r"(addr));
}
__device__ __forceinline__ void mma_f16(float c[4], const uint32_t a[4],
                                        const uint32_t b0, const uint32_t b1) {
    asm volatile(
        "mma.sync.aligned.m16n8k16.row.col.f32.f16.f16.f32 "
        "{%0,%1,%2,%3}, {%4,%5,%6,%7}, {%8,%9}, {%0,%1,%2,%3};\n"
        : "+f"(c[0]), "+f"(c[1]), "+f"(c[2]), "+f"(c[3])
        : "r"(a[0]), "r"(a[1]), "r"(a[2]), "r"(a[3]), "r"(b0), "r"(b1));
}
__device__ __forceinline__ void sts128(uint32_t a, uint32_t v0, uint32_t v1,
                                       uint32_t v2, uint32_t v3) {
    asm volatile("st.shared.v4.b32 [%0], {%1,%2,%3,%4};\n"
                 :: "r"(a), "r"(v0), "r"(v1), "r"(v2), "r"(v3));
}
__device__ __forceinline__ uint32_t pack2(float x, float y) {
    __half2 h = __float22half2_rn(make_float2(x, y));
    return *reinterpret_cast<uint32_t*>(&h);
}
__device__ __forceinline__ float gelu_exact(float x) {
    return 0.5f * x * (1.0f + erff(x * 0.70710678118654752f));
}

// ===========================================================================
// Split-K gather GEMM (fp16 A): CTA 128x64, 4 warps (64x32), 4 CTAs/SM.
// Inner schedule identical to the best-measured round-12 kernel.
// ===========================================================================
template <bool ALIGN16>
__global__ void __launch_bounds__(NTHREADS, 4)
gemm_split(const __half* __restrict__ A, int lda,
           const float* __restrict__ W,
           float* __restrict__ P0, float* __restrict__ P1, int ldp,
           int KSPL, int N)
{
    const int e = blockIdx.z;
    const int cnt = g_cnt[e];
    const int mtile = blockIdx.y % MT;
    const int split = blockIdx.y / MT;
    if (mtile * BM >= cnt) return;
    const int n0 = blockIdx.x * BN;

    const int* idxE = g_idx + e * B_;
    const float* We = W + (size_t)e * (size_t)(KSPL * NSPLIT) * N
                        + (size_t)split * KSPL * N;
    float* Pout = split == 0 ? P0 : P1;

    constexpr uint32_t OFF_A = 0;            // 5 slots
    constexpr uint32_t OFF_B = 5 * SA_B;     // 2 slots

    extern __shared__ char smem_raw[];
    const uint32_t s0 = (uint32_t)__cvta_generic_to_shared(smem_raw);

    const int tid = threadIdx.x;
    const int lane = tid & 31;
    const int warp = tid >> 5;

    // ---- A: one gathered row per thread (128 rows), 2x cp16 ----
    int gm = mtile * BM + tid;
    int gmc = gm < cnt ? gm : cnt - 1;
    const __half* a_h = A + (size_t)idxE[gmc] * lda + split * KSPL;
    const uint32_t a_dst = s0 + OFF_A + (uint32_t)(tid * SAS * 2);

    // ---- B: k-row kB (0..15), 8-float chunk c8 ----
    const int kB = tid >> 3;
    const int c8 = (tid & 7) * 8;
    const float* b_src = We + (size_t)kB * N + n0 + c8;
    const uint32_t b_dst = s0 + OFF_B + (uint32_t)((kB * SBS + c8) * 2);

    const int KT = KSPL / BK;

    float rB[2][8];
    auto ldB = [&](int t, int slot) {
        const float* bs = b_src + (size_t)t * BK * N;
        if (ALIGN16) {
            float4 v0 = *reinterpret_cast<const float4*>(bs);
            float4 v1 = *reinterpret_cast<const float4*>(bs + 4);
            rB[slot][0] = v0.x; rB[slot][1] = v0.y; rB[slot][2] = v0.z; rB[slot][3] = v0.w;
            rB[slot][4] = v1.x; rB[slot][5] = v1.y; rB[slot][6] = v1.z; rB[slot][7] = v1.w;
        } else {
#pragma unroll
            for (int j = 0; j < 4; j++) {
                int gn = n0 + c8 + 2 * j;
                float2 v = (gn < N) ? *reinterpret_cast<const float2*>(bs + 2 * j)
                                    : make_float2(0.f, 0.f);
                rB[slot][2 * j + 0] = v.x; rB[slot][2 * j + 1] = v.y;
            }
        }
    };
    auto stsB = [&](int t, int slot) {
        sts128(b_dst + (uint32_t)((t & 1) * B64_B),
               pack2(rB[slot][0], rB[slot][1]), pack2(rB[slot][2], rB[slot][3]),
               pack2(rB[slot][4], rB[slot][5]), pack2(rB[slot][6], rB[slot][7]));
    };
    auto issueA = [&](int t) {
        const uint32_t ad = a_dst + (uint32_t)((t % 5) * SA_B);
        const __half* as = a_h + (size_t)t * BK;
        cp_async16(ad, as);
        cp_async16(ad + 16, as + 8);
    };

    // ---- warp tiling: 2 warps along M (64), 2 along N (32) ----
    const int wm = (warp & 1) * 64;
    const int wn = (warp >> 1) * 32;
    const int g  = lane >> 2;
    const int tg = lane & 3;

    const uint32_t a_ld0 = s0 + OFF_A +
        (uint32_t)(((wm + (lane & 15)) * SAS + (lane >> 4) * 8) * 2);
    const uint32_t b_ld0 = s0 + OFF_B +
        (uint32_t)(((lane & 15) * SBS + wn + (lane >> 4) * 8) * 2);

    float acc[4][4][4];
#pragma unroll
    for (int mi = 0; mi < 4; mi++)
#pragma unroll
        for (int ni = 0; ni < 4; ni++)
#pragma unroll
            for (int k = 0; k < 4; k++) acc[mi][ni][k] = 0.f;

    // ---- prologue (round-12 schedule) ----
    ldB(0, 0);
    ldB(1, 1);
    issueA(0); cp_commit();
    issueA(1); cp_commit();
    issueA(2); cp_commit();
    issueA(3); cp_commit();
    stsB(0, 0);
    cp_wait<3>();          // A(0) arrived
    __syncthreads();

    for (int t = 0; t < KT; t++) {
        if (t + 2 < KT) ldB(t + 2, t & 1);
        if (t + 1 < KT) stsB(t + 1, (t + 1) & 1);

        const uint32_t a_ld = a_ld0 + (uint32_t)((t % 5) * SA_B);
        const uint32_t b_ld = b_ld0 + (uint32_t)((t & 1) * B64_B);
        uint32_t bf[8];
        ldsm4t(bf,     b_ld);
        ldsm4t(bf + 4, b_ld + 32);
#pragma unroll
        for (int mi = 0; mi < 4; mi++) {
            uint32_t af[4];
            ldsm4(af, a_ld + (uint32_t)(mi * 16 * SAS * 2));
            mma_f16(acc[mi][0], af, bf[0], bf[1]);
            mma_f16(acc[mi][1], af, bf[2], bf[3]);
            mma_f16(acc[mi][2], af, bf[4], bf[5]);
            mma_f16(acc[mi][3], af, bf[6], bf[7]);
        }

        if (t + 4 < KT) issueA(t + 4);
        cp_commit();
        cp_wait<3>();      // A(t+1) arrived
        __syncthreads();
    }

    // ---- epilogue: raw partial store ----
#pragma unroll
    for (int mi = 0; mi < 4; mi++) {
#pragma unroll
        for (int half = 0; half < 2; half++) {
            const int m = wm + mi * 16 + g + half * 8;
            const int gmm = mtile * BM + m;
            if (gmm >= cnt) continue;
            float* op = Pout + (size_t)idxE[gmm] * ldp;
#pragma unroll
            for (int ni = 0; ni < 4; ni++) {
                const int gn = n0 + wn + ni * 8 + tg * 2;
                if (gn + 1 < N) {
                    *reinterpret_cast<float2*>(op + gn) =
                        make_float2(acc[mi][ni][half * 2 + 0],
                                    acc[mi][ni][half * 2 + 1]);
                } else if (gn < N) {
                    op[gn] = acc[mi][ni][half * 2 + 0];
                }
            }
        }
    }
}

// ===========================================================================
__global__ void combine_gelu(const float* __restrict__ P0,
                             const float* __restrict__ P1,
                             const float* __restrict__ bias,
                             __half* __restrict__ dst, int Ncols)
{
    const int r = blockIdx.x;
    const int e = g_bin[r];
    const float* p0 = P0 + (size_t)r * Ncols;
    const float* p1 = P1 + (size_t)r * Ncols;
    const float* be = bias + (size_t)e * Ncols;
    __half* d = dst + (size_t)r * Ncols;
    for (int i = threadIdx.x * 2; i < Ncols; i += 512) {
        float2 a = *reinterpret_cast<const float2*>(p0 + i);
        float2 b = *reinterpret_cast<const float2*>(p1 + i);
        float2 c = *reinterpret_cast<const float2*>(be + i);
        float r0 = gelu_exact(a.x + b.x + c.x);
        float r1 = gelu_exact(a.y + b.y + c.y);
        *reinterpret_cast<__half2*>(d + i) = __float22half2_rn(make_float2(r0, r1));
    }
}

// ===========================================================================
__global__ void logsoftmax_combine(const float* __restrict__ P0,
                                   const float* __restrict__ P1,
                                   const float* __restrict__ b3,
                                   float* __restrict__ out)
{
    const int r = blockIdx.x;
    const int e = g_bin[r];
    const float* p0 = P0 + (size_t)r * CP_;
    const float* p1 = P1 + (size_t)r * CP_;
    const float* be = b3 + (size_t)e * C_;
    float* orow = out + (size_t)r * C_;

    __shared__ float srow[C_];
    __shared__ float sred[256];
    const int tid = threadIdx.x;

    float lmax = -3.4e38f;
    for (int i = tid; i < C_; i += 256) {
        float v = p0[i] + p1[i] + be[i];
        srow[i] = v;
        lmax = fmaxf(lmax, v);
    }
    sred[tid] = lmax;
    __syncthreads();
    for (int s = 128; s > 0; s >>= 1) {
        if (tid < s) sred[tid] = fmaxf(sred[tid], sred[tid + s]);
        __syncthreads();
    }
    const float mx = sred[0];
    __syncthreads();

    float lsum = 0.f;
    for (int i = tid; i < C_; i += 256) lsum += expf(srow[i] - mx);
    sred[tid] = lsum;
    __syncthreads();
    for (int s = 128; s > 0; s >>= 1) {
        if (tid < s) sred[tid] += sred[tid + s];
        __syncthreads();
    }
    const float lse = mx + logf(sred[0]);

    for (int i = tid; i < C_; i += 256) orow[i] = srow[i] - lse;
}

// ---------------------------------------------------------------------------
#define SMEM_G (5 * SA_B + 2 * B64_B)       // 30720 + 4608 = 35328

extern "C" void kernel_launch(void* const* d_in, const int* in_sizes, int n_in,
                              void* d_out, int out_size)
{
    const float* x  = (const float*)d_in[0];
    const float* mf = (const float*)d_in[1];
    const float* W1 = (const float*)d_in[2];
    const float* b1 = (const float*)d_in[3];
    const float* W2 = (const float*)d_in[4];
    const float* b2 = (const float*)d_in[5];
    const float* W3 = (const float*)d_in[6];
    const float* b3 = (const float*)d_in[7];
    float* out = (float*)d_out;

    void *x16p = nullptr, *h1p = nullptr, *h2p = nullptr, *p0p = nullptr, *p1p = nullptr;
    cudaGetSymbolAddress(&x16p, g_x16);
    cudaGetSymbolAddress(&h1p, g_h1);
    cudaGetSymbolAddress(&h2p, g_h2);
    cudaGetSymbolAddress(&p0p, g_p0);
    cudaGetSymbolAddress(&p1p, g_p1);
    __half* x16 = (__half*)x16p;
    __half* h1 = (__half*)h1p;
    __half* h2 = (__half*)h2p;
    float* p0 = (float*)p0p;
    float* p1 = (float*)p1p;

    cudaFuncSetAttribute(gemm_split<true>,
                         cudaFuncAttributeMaxDynamicSharedMemorySize, SMEM_G);
    cudaFuncSetAttribute(gemm_split<false>,
                         cudaFuncAttributeMaxDynamicSharedMemorySize, SMEM_G);

    route_kernel<<<1, B_>>>(mf);
    cvt_x_kernel<<<B_, 256>>>(x);

    // L1: x16 [cnt,1536] @ W1 (split-K 2) -> partials -> gelu -> h1 fp16
    gemm_split<true><<<dim3(H_ / BN, MT * NSPLIT, E_), NTHREADS, SMEM_G>>>(
        x16, D_, W1, p0, p1, H_, D_ / NSPLIT, H_);
    combine_gelu<<<B_, 256>>>(p0, p1, b1, h1, H_);

    // L2: h1 fp16 @ W2 (split-K 2) -> partials -> gelu -> h2 fp16
    gemm_split<true><<<dim3(H_ / BN, MT * NSPLIT, E_), NTHREADS, SMEM_G>>>(
        h1, H_, W2, p0, p1, H_, H_ / NSPLIT, H_);
    combine_gelu<<<B_, 256>>>(p0, p1, b2, h2, H_);

    // L3: h2 fp16 @ W3 (split-K 2) -> partials
    gemm_split<false><<<dim3((C_ + BN - 1) / BN, MT * NSPLIT, E_), NTHREADS, SMEM_G>>>(
        h2, H_, W3, p0, p1, CP_, H_ / NSPLIT, C_);
    logsoftmax_combine<<<B_, 256>>>(p0, p1, b3, out);
}

// round 16
// speedup vs baseline: 1.7785x; 1.7785x over previous
#include <cuda_runtime.h>
#include <cuda_fp16.h>
#include <cstdint>

#define E_ 11
#define B_ 1024
#define D_ 1536
#define H_ 3072
#define C_ 5242
#define CP_ 5248                  // padded partial stride for L3

#define BM 128
#define BN 128
#define BK 16
#define NTHREADS 256
#define MT 2                      // m-tiles per bin
#define NSPLIT 2                  // K splits

#define SAS 24                    // A fp16 tile stride (halves)
#define SA_B (BM * SAS * 2)       // 6144 B per A slot (5 slots)
#define SBS 136                   // B fp16 tile stride (halves)
#define B16_B (BK * SBS * 2)      // 4352 B per B tile (2 tiles)

// ---- scratch (device globals: no allocations allowed) ----
__device__ int    g_cnt[E_];
__device__ int    g_idx[E_ * B_];
__device__ int    g_bin[B_];
__device__ __half g_x16[(size_t)B_ * D_];
__device__ __half g_h1[(size_t)B_ * H_];
__device__ __half g_h2[(size_t)B_ * H_];
__device__ float  g_p0[(size_t)B_ * CP_];
__device__ float  g_p1[(size_t)B_ * CP_];

// ---------------------------------------------------------------------------
__global__ void route_kernel(const float* __restrict__ mf) {
    int tid = threadIdx.x;
    if (tid < E_) g_cnt[tid] = 0;
    __syncthreads();
    float t = 1.0f - mf[tid];
    float q = t / 0.1f;               // IEEE div, matches XLA lowering
    int bin = (int)q;                 // trunc toward zero == astype(int32)
    bin = max(0, min(E_ - 1, bin));
    g_bin[tid] = bin;
    int pos = atomicAdd(&g_cnt[bin], 1);
    g_idx[bin * B_ + pos] = tid;
}

// x fp32 -> fp16 so L1 rides the same fast GEMM path as L2/L3.
__global__ void cvt_x_kernel(const float* __restrict__ x) {
    const int r = blockIdx.x;
    const float* src = x + (size_t)r * D_;
    __half* dst = g_x16 + (size_t)r * D_;
    for (int i = threadIdx.x * 4; i < D_; i += 1024) {
        float4 v = *reinterpret_cast<const float4*>(src + i);
        *reinterpret_cast<__half2*>(dst + i)     = __float22half2_rn(make_float2(v.x, v.y));
        *reinterpret_cast<__half2*>(dst + i + 2) = __float22half2_rn(make_float2(v.z, v.w));
    }
}

// ---- PTX helpers ----------------------------------------------------------
__device__ __forceinline__ void cp_async16(uint32_t s, const void* g) {
    asm volatile("cp.async.cg.shared.global [%0], [%1], 16;\n" :: "r"(s), "l"(g));
}
__device__ __forceinline__ void cp_commit() {
    asm volatile("cp.async.commit_group;\n" ::: "memory");
}
template <int N>
__device__ __forceinline__ void cp_wait() {
    asm volatile("cp.async.wait_group %0;\n" :: "n"(N) : "memory");
}
__device__ __forceinline__ void ldsm4(uint32_t r[4], uint32_t addr) {
    asm volatile("ldmatrix.sync.aligned.m8n8.x4.shared.b16 {%0,%1,%2,%3}, [%4];"
                 : "=r"(r[0]), "=r"(r[1]), "=r"(r[2]), "=r"(r[3]) : "r"(addr));
}
__device__ __forceinline__ void ldsm4t(uint32_t r[4], uint32_t addr) {
    asm volatile("ldmatrix.sync.aligned.m8n8.x4.trans.shared.b16 {%0,%1,%2,%3}, [%4];"
                 : "=r"(r[0]), "=r"(r[1]), "=r"(r[2]), "=r"(r[3]) : "r"(addr));
}
__device__ __forceinline__ void mma_f16(float c[4], const uint32_t a[4],
                                        const uint32_t b0, const uint32_t b1) {
    asm volatile(
        "mma.sync.aligned.m16n8k16.row.col.f32.f16.f16.f32 "
        "{%0,%1,%2,%3}, {%4,%5,%6,%7}, {%8,%9}, {%0,%1,%2,%3};\n"
        : "+f"(c[0]), "+f"(c[1]), "+f"(c[2]), "+f"(c[3])
        : "r"(a[0]), "r"(a[1]), "r"(a[2]), "r"(a[3]), "r"(b0), "r"(b1));
}
__device__ __forceinline__ void sts128(uint32_t a, uint32_t v0, uint32_t v1,
                                       uint32_t v2, uint32_t v3) {
    asm volatile("st.shared.v4.b32 [%0], {%1,%2,%3,%4};\n"
                 :: "r"(a), "r"(v0), "r"(v1), "r"(v2), "r"(v3));
}
__device__ __forceinline__ uint32_t pack2(float x, float y) {
    __half2 h = __float22half2_rn(make_float2(x, y));
    return *reinterpret_cast<uint32_t*>(&h);
}
__device__ __forceinline__ float gelu_exact(float x) {
    return 0.5f * x * (1.0f + erff(x * 0.70710678118654752f));
}

// ===========================================================================
// Split-K gather GEMM (fp16 A) — round-12 proven kernel, unchanged.
// CTA 128x128, 8 warps (64x32 tiles), 2 CTAs/SM. B: LDG fp32 -> reg cvt ->
// STS fp16 (2-slot buffer); A: 5-slot cp.async ring. Raw fp32 partial out.
// ===========================================================================
template <bool ALIGN16>
__global__ void __launch_bounds__(NTHREADS, 2)
gemm_split(const __half* __restrict__ A, int lda,
           const float* __restrict__ W,
           float* __restrict__ P0, float* __restrict__ P1, int ldp,
           int KSPL, int N)
{
    const int e = blockIdx.z;
    const int cnt = g_cnt[e];
    const int mtile = blockIdx.y % MT;
    const int split = blockIdx.y / MT;
    if (mtile * BM >= cnt) return;
    const int n0 = blockIdx.x * BN;

    const int* idxE = g_idx + e * B_;
    const float* We = W + (size_t)e * (size_t)(KSPL * NSPLIT) * N
                        + (size_t)split * KSPL * N;
    float* Pout = split == 0 ? P0 : P1;

    constexpr uint32_t OFF_A = 0;            // 5 slots
    constexpr uint32_t OFF_B = 5 * SA_B;     // 2 tiles

    extern __shared__ char smem_raw[];
    const uint32_t s0 = (uint32_t)__cvta_generic_to_shared(smem_raw);

    const int tid = threadIdx.x;
    const int lane = tid & 31;
    const int warp = tid >> 5;

    // A: one gathered row per thread-pair
    const int rA = tid >> 1;
    const int ha = tid & 1;
    int gm = mtile * BM + rA;
    int gmc = gm < cnt ? gm : cnt - 1;
    const __half* a_h = A + (size_t)idxE[gmc] * lda + split * KSPL + 8 * ha;
    const uint32_t a_dst = s0 + OFF_A + (uint32_t)((rA * SAS + 8 * ha) * 2);

    // B: k-row kB (0..15), 8-float chunk c8
    const int kB = tid >> 4;
    const int c8 = (tid & 15) * 8;
    const float* b_src = We + (size_t)kB * N + n0 + c8;
    const uint32_t b_dst = s0 + OFF_B + (uint32_t)((kB * SBS + c8) * 2);

    const int KT = KSPL / BK;

    float rB[2][8];
    auto ldB = [&](int t, int slot) {
        const float* bs = b_src + (size_t)t * BK * N;
        if (ALIGN16) {
            float4 v0 = *reinterpret_cast<const float4*>(bs);
            float4 v1 = *reinterpret_cast<const float4*>(bs + 4);
            rB[slot][0] = v0.x; rB[slot][1] = v0.y; rB[slot][2] = v0.z; rB[slot][3] = v0.w;
            rB[slot][4] = v1.x; rB[slot][5] = v1.y; rB[slot][6] = v1.z; rB[slot][7] = v1.w;
        } else {
#pragma unroll
            for (int j = 0; j < 4; j++) {
                int gn = n0 + c8 + 2 * j;
                float2 v = (gn < N) ? *reinterpret_cast<const float2*>(bs + 2 * j)
                                    : make_float2(0.f, 0.f);
                rB[slot][2 * j + 0] = v.x; rB[slot][2 * j + 1] = v.y;
            }
        }
    };
    auto stsB = [&](int t, int slot) {
        sts128(b_dst + (uint32_t)((t & 1) * B16_B),
               pack2(rB[slot][0], rB[slot][1]), pack2(rB[slot][2], rB[slot][3]),
               pack2(rB[slot][4], rB[slot][5]), pack2(rB[slot][6], rB[slot][7]));
    };
    auto issueA = [&](int t) {
        cp_async16(a_dst + (uint32_t)((t % 5) * SA_B), a_h + (size_t)t * BK);
    };

    // warp tiling: 2 warps along M (64), 4 along N (32)
    const int wm = (warp & 1) * 64;
    const int wn = (warp >> 1) * 32;
    const int g  = lane >> 2;
    const int tg = lane & 3;

    const uint32_t a_ld0 = s0 + OFF_A +
        (uint32_t)(((wm + (lane & 15)) * SAS + (lane >> 4) * 8) * 2);
    const uint32_t b_ld0 = s0 + OFF_B +
        (uint32_t)(((lane & 15) * SBS + wn + (lane >> 4) * 8) * 2);

    float acc[4][4][4];
#pragma unroll
    for (int mi = 0; mi < 4; mi++)
#pragma unroll
        for (int ni = 0; ni < 4; ni++)
#pragma unroll
            for (int k = 0; k < 4; k++) acc[mi][ni][k] = 0.f;

    // prologue
    ldB(0, 0);
    ldB(1, 1);
    issueA(0); cp_commit();
    issueA(1); cp_commit();
    issueA(2); cp_commit();
    issueA(3); cp_commit();
    stsB(0, 0);
    cp_wait<3>();          // A(0) arrived
    __syncthreads();

    for (int t = 0; t < KT; t++) {
        if (t + 2 < KT) ldB(t + 2, t & 1);
        if (t + 1 < KT) stsB(t + 1, (t + 1) & 1);

        const uint32_t a_ld = a_ld0 + (uint32_t)((t % 5) * SA_B);
        const uint32_t b_ld = b_ld0 + (uint32_t)((t & 1) * B16_B);
        uint32_t bf[8];
        ldsm4t(bf,     b_ld);
        ldsm4t(bf + 4, b_ld + 32);
#pragma unroll
        for (int mi = 0; mi < 4; mi++) {
            uint32_t af[4];
            ldsm4(af, a_ld + (uint32_t)(mi * 16 * SAS * 2));
            mma_f16(acc[mi][0], af, bf[0], bf[1]);
            mma_f16(acc[mi][1], af, bf[2], bf[3]);
            mma_f16(acc[mi][2], af, bf[4], bf[5]);
            mma_f16(acc[mi][3], af, bf[6], bf[7]);
        }

        if (t + 4 < KT) issueA(t + 4);
        cp_commit();
        cp_wait<3>();      // A(t+1) arrived
        __syncthreads();
    }

    // epilogue: raw partial store
#pragma unroll
    for (int mi = 0; mi < 4; mi++) {
#pragma unroll
        for (int half = 0; half < 2; half++) {
            const int m = wm + mi * 16 + g + half * 8;
            const int gmm = mtile * BM + m;
            if (gmm >= cnt) continue;
            float* op = Pout + (size_t)idxE[gmm] * ldp;
#pragma unroll
            for (int ni = 0; ni < 4; ni++) {
                const int gn = n0 + wn + ni * 8 + tg * 2;
                if (gn + 1 < N) {
                    *reinterpret_cast<float2*>(op + gn) =
                        make_float2(acc[mi][ni][half * 2 + 0],
                                    acc[mi][ni][half * 2 + 1]);
                } else if (gn < N) {
                    op[gn] = acc[mi][ni][half * 2 + 0];
                }
            }
        }
    }
}

// ===========================================================================
// Combine p0+p1+bias -> gelu -> fp16 (for h1 / h2)
// ===========================================================================
__global__ void combine_gelu(const float* __restrict__ P0,
                             const float* __restrict__ P1,
                             const float* __restrict__ bias,
                             __half* __restrict__ dst, int Ncols)
{
    const int r = blockIdx.x;
    const int e = g_bin[r];
    const float* p0 = P0 + (size_t)r * Ncols;
    const float* p1 = P1 + (size_t)r * Ncols;
    const float* be = bias + (size_t)e * Ncols;
    __half* d = dst + (size_t)r * Ncols;
    for (int i = threadIdx.x * 2; i < Ncols; i += 512) {
        float2 a = *reinterpret_cast<const float2*>(p0 + i);
        float2 b = *reinterpret_cast<const float2*>(p1 + i);
        float2 c = *reinterpret_cast<const float2*>(be + i);
        float r0 = gelu_exact(a.x + b.x + c.x);
        float r1 = gelu_exact(a.y + b.y + c.y);
        *reinterpret_cast<__half2*>(d + i) = __float22half2_rn(make_float2(r0, r1));
    }
}

// ===========================================================================
// Fused L3 combine + log_softmax.
// ===========================================================================
__global__ void logsoftmax_combine(const float* __restrict__ P0,
                                   const float* __restrict__ P1,
                                   const float* __restrict__ b3,
                                   float* __restrict__ out)
{
    const int r = blockIdx.x;
    const int e = g_bin[r];
    const float* p0 = P0 + (size_t)r * CP_;
    const float* p1 = P1 + (size_t)r * CP_;
    const float* be = b3 + (size_t)e * C_;
    float* orow = out + (size_t)r * C_;

    __shared__ float srow[C_];
    __shared__ float sred[256];
    const int tid = threadIdx.x;

    float lmax = -3.4e38f;
    for (int i = tid; i < C_; i += 256) {
        float v = p0[i] + p1[i] + be[i];
        srow[i] = v;
        lmax = fmaxf(lmax, v);
    }
    sred[tid] = lmax;
    __syncthreads();
    for (int s = 128; s > 0; s >>= 1) {
        if (tid < s) sred[tid] = fmaxf(sred[tid], sred[tid + s]);
        __syncthreads();
    }
    const float mx = sred[0];
    __syncthreads();

    float lsum = 0.f;
    for (int i = tid; i < C_; i += 256) lsum += expf(srow[i] - mx);
    sred[tid] = lsum;
    __syncthreads();
    for (int s = 128; s > 0; s >>= 1) {
        if (tid < s) sred[tid] += sred[tid + s];
        __syncthreads();
    }
    const float lse = mx + logf(sred[0]);

    for (int i = tid; i < C_; i += 256) orow[i] = srow[i] - lse;
}

// ---------------------------------------------------------------------------
#define SMEM_G (5 * SA_B + 2 * B16_B)       // 30720 + 8704 = 39424

extern "C" void kernel_launch(void* const* d_in, const int* in_sizes, int n_in,
                              void* d_out, int out_size)
{
    const float* x  = (const float*)d_in[0];
    const float* mf = (const float*)d_in[1];
    const float* W1 = (const float*)d_in[2];
    const float* b1 = (const float*)d_in[3];
    const float* W2 = (const float*)d_in[4];
    const float* b2 = (const float*)d_in[5];
    const float* W3 = (const float*)d_in[6];
    const float* b3 = (const float*)d_in[7];
    float* out = (float*)d_out;

    void *x16p = nullptr, *h1p = nullptr, *h2p = nullptr, *p0p = nullptr, *p1p = nullptr;
    cudaGetSymbolAddress(&x16p, g_x16);
    cudaGetSymbolAddress(&h1p, g_h1);
    cudaGetSymbolAddress(&h2p, g_h2);
    cudaGetSymbolAddress(&p0p, g_p0);
    cudaGetSymbolAddress(&p1p, g_p1);
    __half* x16 = (__half*)x16p;
    __half* h1 = (__half*)h1p;
    __half* h2 = (__half*)h2p;
    float* p0 = (float*)p0p;
    float* p1 = (float*)p1p;

    cudaFuncSetAttribute(gemm_split<true>,
                         cudaFuncAttributeMaxDynamicSharedMemorySize, SMEM_G);
    cudaFuncSetAttribute(gemm_split<false>,
                         cudaFuncAttributeMaxDynamicSharedMemorySize, SMEM_G);

    route_kernel<<<1, B_>>>(mf);
    cvt_x_kernel<<<B_, 256>>>(x);

    // L1: x16 [cnt,1536] @ W1 (split-K 2) -> partials -> gelu -> h1 fp16
    gemm_split<true><<<dim3(H_ / BN, MT * NSPLIT, E_), NTHREADS, SMEM_G>>>(
        x16, D_, W1, p0, p1, H_, D_ / NSPLIT, H_);
    combine_gelu<<<B_, 256>>>(p0, p1, b1, h1, H_);

    // L2: h1 fp16 @ W2 (split-K 2) -> partials -> gelu -> h2 fp16
    gemm_split<true><<<dim3(H_ / BN, MT * NSPLIT, E_), NTHREADS, SMEM_G>>>(
        h1, H_, W2, p0, p1, H_, H_ / NSPLIT, H_);
    combine_gelu<<<B_, 256>>>(p0, p1, b2, h2, H_);

    // L3: h2 fp16 @ W3 (split-K 2) -> partials
    gemm_split<false><<<dim3((C_ + BN - 1) / BN, MT * NSPLIT, E_), NTHREADS, SMEM_G>>>(
        h2, H_, W3, p0, p1, CP_, H_ / NSPLIT, C_);
    logsoftmax_combine<<<B_, 256>>>(p0, p1, b3, out);
}

// round 17
// speedup vs baseline: 1.8040x; 1.0143x over previous
#include <cuda_runtime.h>
#include <cuda_fp16.h>
#include <cstdint>

#define E_ 11
#define B_ 1024
#define D_ 1536
#define H_ 3072
#define C_ 5242
#define CP_ 5248                  // padded partial stride for L3

#define BM 128
#define BN 128
#define BK 16
#define NTHREADS 256
#define MT 2                      // m-tiles per bin
#define NSPL12 2                  // K splits for L1/L2
#define NSPL3 4                   // K splits for L3

#define SAS 24                    // A fp16 tile stride (halves)
#define SA_B (BM * SAS * 2)       // 6144 B per A slot (5 slots)
#define SBS 136                   // B fp16 tile stride (halves)
#define B16_B (BK * SBS * 2)      // 4352 B per B tile (2 tiles)

// ---- scratch (device globals: no allocations allowed) ----
__device__ int    g_cnt[E_];
__device__ int    g_idx[E_ * B_];
__device__ int    g_bin[B_];
__device__ __half g_x16[(size_t)B_ * D_];
__device__ __half g_h1[(size_t)B_ * H_];
__device__ __half g_h2[(size_t)B_ * H_];
__device__ float  g_p0[(size_t)B_ * CP_];
__device__ float  g_p1[(size_t)B_ * CP_];
__device__ float  g_p2[(size_t)B_ * CP_];
__device__ float  g_p3[(size_t)B_ * CP_];

// ---------------------------------------------------------------------------
__global__ void route_kernel(const float* __restrict__ mf) {
    int tid = threadIdx.x;
    if (tid < E_) g_cnt[tid] = 0;
    __syncthreads();
    float t = 1.0f - mf[tid];
    float q = t / 0.1f;               // IEEE div, matches XLA lowering
    int bin = (int)q;                 // trunc toward zero == astype(int32)
    bin = max(0, min(E_ - 1, bin));
    g_bin[tid] = bin;
    int pos = atomicAdd(&g_cnt[bin], 1);
    g_idx[bin * B_ + pos] = tid;
}

// x fp32 -> fp16 so L1 rides the same fast GEMM path as L2/L3.
__global__ void cvt_x_kernel(const float* __restrict__ x) {
    const int r = blockIdx.x;
    const float* src = x + (size_t)r * D_;
    __half* dst = g_x16 + (size_t)r * D_;
    for (int i = threadIdx.x * 4; i < D_; i += 1024) {
        float4 v = *reinterpret_cast<const float4*>(src + i);
        *reinterpret_cast<__half2*>(dst + i)     = __float22half2_rn(make_float2(v.x, v.y));
        *reinterpret_cast<__half2*>(dst + i + 2) = __float22half2_rn(make_float2(v.z, v.w));
    }
}

// ---- PTX helpers ----------------------------------------------------------
__device__ __forceinline__ void cp_async16(uint32_t s, const void* g) {
    asm volatile("cp.async.cg.shared.global [%0], [%1], 16;\n" :: "r"(s), "l"(g));
}
__device__ __forceinline__ void cp_commit() {
    asm volatile("cp.async.commit_group;\n" ::: "memory");
}
template <int N>
__device__ __forceinline__ void cp_wait() {
    asm volatile("cp.async.wait_group %0;\n" :: "n"(N) : "memory");
}
__device__ __forceinline__ void ldsm4(uint32_t r[4], uint32_t addr) {
    asm volatile("ldmatrix.sync.aligned.m8n8.x4.shared.b16 {%0,%1,%2,%3}, [%4];"
                 : "=r"(r[0]), "=r"(r[1]), "=r"(r[2]), "=r"(r[3]) : "r"(addr));
}
__device__ __forceinline__ void ldsm4t(uint32_t r[4], uint32_t addr) {
    asm volatile("ldmatrix.sync.aligned.m8n8.x4.trans.shared.b16 {%0,%1,%2,%3}, [%4];"
                 : "=r"(r[0]), "=r"(r[1]), "=r"(r[2]), "=r"(r[3]) : "r"(addr));
}
__device__ __forceinline__ void mma_f16(float c[4], const uint32_t a[4],
                                        const uint32_t b0, const uint32_t b1) {
    asm volatile(
        "mma.sync.aligned.m16n8k16.row.col.f32.f16.f16.f32 "
        "{%0,%1,%2,%3}, {%4,%5,%6,%7}, {%8,%9}, {%0,%1,%2,%3};\n"
        : "+f"(c[0]), "+f"(c[1]), "+f"(c[2]), "+f"(c[3])
        : "r"(a[0]), "r"(a[1]), "r"(a[2]), "r"(a[3]), "r"(b0), "r"(b1));
}
__device__ __forceinline__ void sts128(uint32_t a, uint32_t v0, uint32_t v1,
                                       uint32_t v2, uint32_t v3) {
    asm volatile("st.shared.v4.b32 [%0], {%1,%2,%3,%4};\n"
                 :: "r"(a), "r"(v0), "r"(v1), "r"(v2), "r"(v3));
}
__device__ __forceinline__ uint32_t pack2(float x, float y) {
    __half2 h = __float22half2_rn(make_float2(x, y));
    return *reinterpret_cast<uint32_t*>(&h);
}
__device__ __forceinline__ float gelu_exact(float x) {
    return 0.5f * x * (1.0f + erff(x * 0.70710678118654752f));
}

// ===========================================================================
// Split-K gather GEMM (fp16 A) — round-12/16 proven inner loop, unchanged.
// CTA 128x128, 8 warps (64x32 tiles), 2 CTAs/SM. blockIdx.y = split*MT+mtile;
// partial output selected from P0..P3 by split index.
// ===========================================================================
template <bool ALIGN16>
__global__ void __launch_bounds__(NTHREADS, 2)
gemm_split(const __half* __restrict__ A, int lda,
           const float* __restrict__ W,
           float* __restrict__ P0, float* __restrict__ P1,
           float* __restrict__ P2, float* __restrict__ P3, int ldp,
           int KSPL, int Ktot, int N)
{
    const int e = blockIdx.z;
    const int cnt = g_cnt[e];
    const int mtile = blockIdx.y % MT;
    const int split = blockIdx.y / MT;
    if (mtile * BM >= cnt) return;
    const int n0 = blockIdx.x * BN;

    const int* idxE = g_idx + e * B_;
    const float* We = W + (size_t)e * (size_t)Ktot * N
                        + (size_t)split * KSPL * N;
    float* Pout = (split == 0) ? P0 : (split == 1) ? P1 : (split == 2) ? P2 : P3;

    constexpr uint32_t OFF_A = 0;            // 5 slots
    constexpr uint32_t OFF_B = 5 * SA_B;     // 2 tiles

    extern __shared__ char smem_raw[];
    const uint32_t s0 = (uint32_t)__cvta_generic_to_shared(smem_raw);

    const int tid = threadIdx.x;
    const int lane = tid & 31;
    const int warp = tid >> 5;

    // A: one gathered row per thread-pair
    const int rA = tid >> 1;
    const int ha = tid & 1;
    int gm = mtile * BM + rA;
    int gmc = gm < cnt ? gm : cnt - 1;
    const __half* a_h = A + (size_t)idxE[gmc] * lda + split * KSPL + 8 * ha;
    const uint32_t a_dst = s0 + OFF_A + (uint32_t)((rA * SAS + 8 * ha) * 2);

    // B: k-row kB (0..15), 8-float chunk c8
    const int kB = tid >> 4;
    const int c8 = (tid & 15) * 8;
    const float* b_src = We + (size_t)kB * N + n0 + c8;
    const uint32_t b_dst = s0 + OFF_B + (uint32_t)((kB * SBS + c8) * 2);

    const int KT = KSPL / BK;

    float rB[2][8];
    auto ldB = [&](int t, int slot) {
        const float* bs = b_src + (size_t)t * BK * N;
        if (ALIGN16) {
            float4 v0 = *reinterpret_cast<const float4*>(bs);
            float4 v1 = *reinterpret_cast<const float4*>(bs + 4);
            rB[slot][0] = v0.x; rB[slot][1] = v0.y; rB[slot][2] = v0.z; rB[slot][3] = v0.w;
            rB[slot][4] = v1.x; rB[slot][5] = v1.y; rB[slot][6] = v1.z; rB[slot][7] = v1.w;
        } else {
#pragma unroll
            for (int j = 0; j < 4; j++) {
                int gn = n0 + c8 + 2 * j;
                float2 v = (gn < N) ? *reinterpret_cast<const float2*>(bs + 2 * j)
                                    : make_float2(0.f, 0.f);
                rB[slot][2 * j + 0] = v.x; rB[slot][2 * j + 1] = v.y;
            }
        }
    };
    auto stsB = [&](int t, int slot) {
        sts128(b_dst + (uint32_t)((t & 1) * B16_B),
               pack2(rB[slot][0], rB[slot][1]), pack2(rB[slot][2], rB[slot][3]),
               pack2(rB[slot][4], rB[slot][5]), pack2(rB[slot][6], rB[slot][7]));
    };
    auto issueA = [&](int t) {
        cp_async16(a_dst + (uint32_t)((t % 5) * SA_B), a_h + (size_t)t * BK);
    };

    // warp tiling: 2 warps along M (64), 4 along N (32)
    const int wm = (warp & 1) * 64;
    const int wn = (warp >> 1) * 32;
    const int g  = lane >> 2;
    const int tg = lane & 3;

    const uint32_t a_ld0 = s0 + OFF_A +
        (uint32_t)(((wm + (lane & 15)) * SAS + (lane >> 4) * 8) * 2);
    const uint32_t b_ld0 = s0 + OFF_B +
        (uint32_t)(((lane & 15) * SBS + wn + (lane >> 4) * 8) * 2);

    float acc[4][4][4];
#pragma unroll
    for (int mi = 0; mi < 4; mi++)
#pragma unroll
        for (int ni = 0; ni < 4; ni++)
#pragma unroll
            for (int k = 0; k < 4; k++) acc[mi][ni][k] = 0.f;

    // prologue
    ldB(0, 0);
    ldB(1, 1);
    issueA(0); cp_commit();
    issueA(1); cp_commit();
    issueA(2); cp_commit();
    issueA(3); cp_commit();
    stsB(0, 0);
    cp_wait<3>();          // A(0) arrived
    __syncthreads();

    for (int t = 0; t < KT; t++) {
        if (t + 2 < KT) ldB(t + 2, t & 1);
        if (t + 1 < KT) stsB(t + 1, (t + 1) & 1);

        const uint32_t a_ld = a_ld0 + (uint32_t)((t % 5) * SA_B);
        const uint32_t b_ld = b_ld0 + (uint32_t)((t & 1) * B16_B);
        uint32_t bf[8];
        ldsm4t(bf,     b_ld);
        ldsm4t(bf + 4, b_ld + 32);
#pragma unroll
        for (int mi = 0; mi < 4; mi++) {
            uint32_t af[4];
            ldsm4(af, a_ld + (uint32_t)(mi * 16 * SAS * 2));
            mma_f16(acc[mi][0], af, bf[0], bf[1]);
            mma_f16(acc[mi][1], af, bf[2], bf[3]);
            mma_f16(acc[mi][2], af, bf[4], bf[5]);
            mma_f16(acc[mi][3], af, bf[6], bf[7]);
        }

        if (t + 4 < KT) issueA(t + 4);
        cp_commit();
        cp_wait<3>();      // A(t+1) arrived
        __syncthreads();
    }

    // epilogue: raw partial store
#pragma unroll
    for (int mi = 0; mi < 4; mi++) {
#pragma unroll
        for (int half = 0; half < 2; half++) {
            const int m = wm + mi * 16 + g + half * 8;
            const int gmm = mtile * BM + m;
            if (gmm >= cnt) continue;
            float* op = Pout + (size_t)idxE[gmm] * ldp;
#pragma unroll
            for (int ni = 0; ni < 4; ni++) {
                const int gn = n0 + wn + ni * 8 + tg * 2;
                if (gn + 1 < N) {
                    *reinterpret_cast<float2*>(op + gn) =
                        make_float2(acc[mi][ni][half * 2 + 0],
                                    acc[mi][ni][half * 2 + 1]);
                } else if (gn < N) {
                    op[gn] = acc[mi][ni][half * 2 + 0];
                }
            }
        }
    }
}

// ===========================================================================
// Combine p0+p1+bias -> gelu -> fp16 (for h1 / h2)
// ===========================================================================
__global__ void combine_gelu(const float* __restrict__ P0,
                             const float* __restrict__ P1,
                             const float* __restrict__ bias,
                             __half* __restrict__ dst, int Ncols)
{
    const int r = blockIdx.x;
    const int e = g_bin[r];
    const float* p0 = P0 + (size_t)r * Ncols;
    const float* p1 = P1 + (size_t)r * Ncols;
    const float* be = bias + (size_t)e * Ncols;
    __half* d = dst + (size_t)r * Ncols;
    for (int i = threadIdx.x * 2; i < Ncols; i += 512) {
        float2 a = *reinterpret_cast<const float2*>(p0 + i);
        float2 b = *reinterpret_cast<const float2*>(p1 + i);
        float2 c = *reinterpret_cast<const float2*>(be + i);
        float r0 = gelu_exact(a.x + b.x + c.x);
        float r1 = gelu_exact(a.y + b.y + c.y);
        *reinterpret_cast<__half2*>(d + i) = __float22half2_rn(make_float2(r0, r1));
    }
}

// ===========================================================================
// Fused L3 combine (4 partials) + log_softmax.
// ===========================================================================
__global__ void logsoftmax_combine4(const float* __restrict__ P0,
                                    const float* __restrict__ P1,
                                    const float* __restrict__ P2,
                                    const float* __restrict__ P3,
                                    const float* __restrict__ b3,
                                    float* __restrict__ out)
{
    const int r = blockIdx.x;
    const int e = g_bin[r];
    const float* p0 = P0 + (size_t)r * CP_;
    const float* p1 = P1 + (size_t)r * CP_;
    const float* p2 = P2 + (size_t)r * CP_;
    const float* p3 = P3 + (size_t)r * CP_;
    const float* be = b3 + (size_t)e * C_;
    float* orow = out + (size_t)r * C_;

    __shared__ float srow[C_];
    __shared__ float sred[256];
    const int tid = threadIdx.x;

    float lmax = -3.4e38f;
    for (int i = tid; i < C_; i += 256) {
        float v = ((p0[i] + p1[i]) + (p2[i] + p3[i])) + be[i];
        srow[i] = v;
        lmax = fmaxf(lmax, v);
    }
    sred[tid] = lmax;
    __syncthreads();
    for (int s = 128; s > 0; s >>= 1) {
        if (tid < s) sred[tid] = fmaxf(sred[tid], sred[tid + s]);
        __syncthreads();
    }
    const float mx = sred[0];
    __syncthreads();

    float lsum = 0.f;
    for (int i = tid; i < C_; i += 256) lsum += expf(srow[i] - mx);
    sred[tid] = lsum;
    __syncthreads();
    for (int s = 128; s > 0; s >>= 1) {
        if (tid < s) sred[tid] += sred[tid + s];
        __syncthreads();
    }
    const float lse = mx + logf(sred[0]);

    for (int i = tid; i < C_; i += 256) orow[i] = srow[i] - lse;
}

// ---------------------------------------------------------------------------
#define SMEM_G (5 * SA_B + 2 * B16_B)       // 30720 + 8704 = 39424

extern "C" void kernel_launch(void* const* d_in, const int* in_sizes, int n_in,
                              void* d_out, int out_size)
{
    const float* x  = (const float*)d_in[0];
    const float* mf = (const float*)d_in[1];
    const float* W1 = (const float*)d_in[2];
    const float* b1 = (const float*)d_in[3];
    const float* W2 = (const float*)d_in[4];
    const float* b2 = (const float*)d_in[5];
    const float* W3 = (const float*)d_in[6];
    const float* b3 = (const float*)d_in[7];
    float* out = (float*)d_out;

    void *x16p = nullptr, *h1p = nullptr, *h2p = nullptr;
    void *p0p = nullptr, *p1p = nullptr, *p2p = nullptr, *p3p = nullptr;
    cudaGetSymbolAddress(&x16p, g_x16);
    cudaGetSymbolAddress(&h1p, g_h1);
    cudaGetSymbolAddress(&h2p, g_h2);
    cudaGetSymbolAddress(&p0p, g_p0);
    cudaGetSymbolAddress(&p1p, g_p1);
    cudaGetSymbolAddress(&p2p, g_p2);
    cudaGetSymbolAddress(&p3p, g_p3);
    __half* x16 = (__half*)x16p;
    __half* h1 = (__half*)h1p;
    __half* h2 = (__half*)h2p;
    float* p0 = (float*)p0p;
    float* p1 = (float*)p1p;
    float* p2 = (float*)p2p;
    float* p3 = (float*)p3p;

    cudaFuncSetAttribute(gemm_split<true>,
                         cudaFuncAttributeMaxDynamicSharedMemorySize, SMEM_G);
    cudaFuncSetAttribute(gemm_split<false>,
                         cudaFuncAttributeMaxDynamicSharedMemorySize, SMEM_G);

    route_kernel<<<1, B_>>>(mf);
    cvt_x_kernel<<<B_, 256>>>(x);

    // L1: x16 [cnt,1536] @ W1 (split-K 2) -> p0,p1 -> gelu -> h1 fp16
    gemm_split<true><<<dim3(H_ / BN, MT * NSPL12, E_), NTHREADS, SMEM_G>>>(
        x16, D_, W1, p0, p1, p2, p3, H_, D_ / NSPL12, D_, H_);
    combine_gelu<<<B_, 256>>>(p0, p1, b1, h1, H_);

    // L2: h1 fp16 @ W2 (split-K 2) -> p0,p1 -> gelu -> h2 fp16
    gemm_split<true><<<dim3(H_ / BN, MT * NSPL12, E_), NTHREADS, SMEM_G>>>(
        h1, H_, W2, p0, p1, p2, p3, H_, H_ / NSPL12, H_, H_);
    combine_gelu<<<B_, 256>>>(p0, p1, b2, h2, H_);

    // L3: h2 fp16 @ W3 (split-K 4) -> p0..p3
    gemm_split<false><<<dim3((C_ + BN - 1) / BN, MT * NSPL3, E_), NTHREADS, SMEM_G>>>(
        h2, H_, W3, p0, p1, p2, p3, CP_, H_ / NSPL3, H_, C_);
    logsoftmax_combine4<<<B_, 256>>>(p0, p1, p2, p3, b3, out);
}